// round 14
// baseline (speedup 1.0000x reference)
#include <cuda_runtime.h>
#include <cuda_bf16.h>
#include <cstdint>

#define OPT 64
#define DIN 128
#define DOUT 128
#define TILE_M 64
#define MAX_B 16384
#define HBLK 16
#define MAX_TILES (MAX_B / TILE_M + OPT)      // 320

// ---- scratch (device allocation banned) ----
__device__ int g_blockhist[HBLK][OPT];
__device__ int g_rowids[MAX_B];
__device__ int g_histflag[HBLK];   // zero-init; reset by last scatter block each launch
__device__ int g_scatcnt;
__device__ int g_ntiles;
__device__ int g_tile_e[MAX_TILES];
__device__ int g_tile_m0[MAX_TILES];
__device__ int g_tile_mc[MAX_TILES];
// pre-split bf16 operands
__device__ __align__(16) __nv_bfloat16 g_xhi[MAX_B * DIN];
__device__ __align__(16) __nv_bfloat16 g_xlo[MAX_B * DIN];
__device__ __align__(16) __nv_bfloat16 g_whi[OPT * DIN * DOUT];
__device__ __align__(16) __nv_bfloat16 g_wlo[OPT * DIN * DOUT];

__device__ __forceinline__ uint32_t pack_bf2(__nv_bfloat16 lo, __nv_bfloat16 hi) {
    return ((uint32_t)__bfloat16_as_ushort(hi) << 16) | __bfloat16_as_ushort(lo);
}

__device__ __forceinline__ void split8(const float* vv, uint4& ph4, uint4& pl4) {
    uint32_t ph[4], pl[4];
    #pragma unroll
    for (int j = 0; j < 4; j++) {
        __nv_bfloat16 h0 = __float2bfloat16_rn(vv[2 * j]);
        __nv_bfloat16 h1 = __float2bfloat16_rn(vv[2 * j + 1]);
        __nv_bfloat16 l0 = __float2bfloat16_rn(vv[2 * j] - __bfloat162float(h0));
        __nv_bfloat16 l1 = __float2bfloat16_rn(vv[2 * j + 1] - __bfloat162float(h1));
        ph[j] = pack_bf2(h0, h1);
        pl[j] = pack_bf2(l0, l1);
    }
    ph4 = make_uint4(ph[0], ph[1], ph[2], ph[3]);
    pl4 = make_uint4(pl[0], pl[1], pl[2], pl[3]);
}

// ---------------- K1: hist | scatter+tilemap | convert, one launch ----------------

#define K1_BLOCKS 256
#define CONV0 32                               // first converter block

__global__ void prep_kernel(const int* __restrict__ idx,
                            const float* __restrict__ x,
                            const float* __restrict__ w, int B) {
    int t = threadIdx.x;
    int b = blockIdx.x;

    if (b < HBLK) {
        // ---- histogram of slab b ----
        __shared__ int h[OPT];
        if (t < OPT) h[t] = 0;
        __syncthreads();
        int i4 = b * 256 + t;
        if (i4 * 4 + 3 < B) {
            int4 v = ((const int4*)idx)[i4];
            if (v.x >= 0 && v.x < OPT) atomicAdd(&h[v.x], 1);
            if (v.y >= 0 && v.y < OPT) atomicAdd(&h[v.y], 1);
            if (v.z >= 0 && v.z < OPT) atomicAdd(&h[v.z], 1);
            if (v.w >= 0 && v.w < OPT) atomicAdd(&h[v.w], 1);
        } else {
            for (int i = i4 * 4; i < min(i4 * 4 + 4, B); i++) {
                int e = idx[i];
                if (e >= 0 && e < OPT) atomicAdd(&h[e], 1);
            }
        }
        __syncthreads();
        if (t < OPT) g_blockhist[b][t] = h[t];
        __threadfence();
        __syncthreads();
        if (t == 0) {
            asm volatile("st.global.release.gpu.b32 [%0], %1;"
                         :: "l"(&g_histflag[b]), "r"(1) : "memory");
        }
    } else if (b < CONV0) {
        // ---- scatter block for slab j; block 16 also writes the tile map ----
        int j = b - HBLK;
        __shared__ int tot[OPT], off[OPT], cur[OPT];
        if (t < HBLK) {
            int v;
            do {
                asm volatile("ld.global.acquire.gpu.b32 %0, [%1];"
                             : "=r"(v) : "l"(&g_histflag[t]) : "memory");
            } while (v == 0);
        }
        __syncthreads();
        if (t < OPT) {
            int s = 0;
            #pragma unroll
            for (int bb = 0; bb < HBLK; bb++) s += g_blockhist[bb][t];
            tot[t] = s;
        }
        __syncthreads();
        if (t == 0) {
            int a = 0;
            for (int e = 0; e < OPT; e++) { off[e] = a; a += tot[e]; }
            if (j == 0) {
                int ta = 0;
                for (int e = 0; e < OPT; e++) {
                    int rem = tot[e];
                    int base = off[e];
                    while (rem > 0) {
                        g_tile_e[ta] = e;
                        g_tile_m0[ta] = base;
                        g_tile_mc[ta] = min(rem, TILE_M);
                        base += TILE_M; rem -= TILE_M; ta++;
                    }
                }
                g_ntiles = ta;
            }
        }
        __syncthreads();
        if (t < OPT) {
            int pre = off[t];
            for (int bb = 0; bb < j; bb++) pre += g_blockhist[bb][t];
            cur[t] = pre;
        }
        __syncthreads();
        int i4 = j * 256 + t;
        if (i4 * 4 + 3 < B) {
            int4 v = ((const int4*)idx)[i4];
            int es[4] = {v.x, v.y, v.z, v.w};
            #pragma unroll
            for (int q = 0; q < 4; q++) {
                int e = es[q];
                if (e >= 0 && e < OPT) {
                    int r = atomicAdd(&cur[e], 1);
                    g_rowids[r] = i4 * 4 + q;
                }
            }
        } else {
            for (int i = i4 * 4; i < min(i4 * 4 + 4, B); i++) {
                int e = idx[i];
                if (e >= 0 && e < OPT) {
                    int r = atomicAdd(&cur[e], 1);
                    g_rowids[r] = i;
                }
            }
        }
        __threadfence();
        __syncthreads();
        if (t == 0) {
            int n = atomicAdd(&g_scatcnt, 1);
            if (n == HBLK - 1) {           // last scatter block: reset for next replay
                for (int bb = 0; bb < HBLK; bb++) g_histflag[bb] = 0;
                g_scatcnt = 0;
            }
        }
    } else {
        // ---- converters: x then w, flat 8-float chunks ----
        int nxc = B * DIN / 8;
        int nwc = OPT * DIN * DOUT / 8;
        int start = (b - CONV0) * 256 + t;
        int stride = (K1_BLOCKS - CONV0) * 256;
        for (int i = start; i < nxc + nwc; i += stride) {
            if (i < nxc) {
                const float* s = x + (size_t)i * 8;
                float4 v0 = *(const float4*)(s);
                float4 v1 = *(const float4*)(s + 4);
                float vv[8] = {v0.x, v0.y, v0.z, v0.w, v1.x, v1.y, v1.z, v1.w};
                uint4 ph4, pl4;
                split8(vv, ph4, pl4);
                *(uint4*)(g_xhi + (size_t)i * 8) = ph4;
                *(uint4*)(g_xlo + (size_t)i * 8) = pl4;
            } else {
                size_t jj = (size_t)(i - nxc) * 8;
                const float* s = w + jj;
                float4 v0 = *(const float4*)(s);
                float4 v1 = *(const float4*)(s + 4);
                float vv[8] = {v0.x, v0.y, v0.z, v0.w, v1.x, v1.y, v1.z, v1.w};
                uint4 ph4, pl4;
                split8(vv, ph4, pl4);
                *(uint4*)(g_whi + jj) = ph4;
                *(uint4*)(g_wlo + jj) = pl4;
            }
        }
    }
}

// ---------------- K2: pure GEMM, zero bookkeeping ----------------
// Tile 64(M) x 128(N) x 128(K). 8 warps 2x4. 2 blocks/SM.

#define LDA 136
#define SA_HI 0
#define SA_LO (TILE_M * LDA * 2)                      // 17408
#define SB_HI (2 * TILE_M * LDA * 2)                  // 34816
#define SB_LO (2 * TILE_M * LDA * 2 + DIN * LDA * 2)  // 69632
#define SROW  (2 * TILE_M * LDA * 2 + 2 * DIN * LDA * 2)  // 104448
#define SBIAS (SROW + 256)
#define SMEM_BYTES (SBIAS + 512)                      // 105216
#define NT 256

__device__ __forceinline__ uint32_t smem_u32(const void* p) {
    uint32_t a;
    asm("{ .reg .u64 tmp; cvta.to.shared.u64 tmp, %1; cvt.u32.u64 %0, tmp; }"
        : "=r"(a) : "l"(p));
    return a;
}

__device__ __forceinline__ void cp16(uint32_t dst, const void* src) {
    asm volatile("cp.async.cg.shared.global [%0], [%1], 16;"
                 :: "r"(dst), "l"(src) : "memory");
}

__device__ __forceinline__ void ldsm_x4(uint32_t* r, uint32_t addr) {
    asm volatile("ldmatrix.sync.aligned.m8n8.x4.shared.b16 {%0,%1,%2,%3}, [%4];"
        : "=r"(r[0]), "=r"(r[1]), "=r"(r[2]), "=r"(r[3]) : "r"(addr));
}

__device__ __forceinline__ void ldsm_x4t(uint32_t* r, uint32_t addr) {
    asm volatile("ldmatrix.sync.aligned.m8n8.x4.trans.shared.b16 {%0,%1,%2,%3}, [%4];"
        : "=r"(r[0]), "=r"(r[1]), "=r"(r[2]), "=r"(r[3]) : "r"(addr));
}

__device__ __forceinline__ void mma_bf16(float* c, const uint32_t* a, const uint32_t* b) {
    asm volatile(
        "mma.sync.aligned.m16n8k16.row.col.f32.bf16.bf16.f32 "
        "{%0,%1,%2,%3}, {%4,%5,%6,%7}, {%8,%9}, {%0,%1,%2,%3};"
        : "+f"(c[0]), "+f"(c[1]), "+f"(c[2]), "+f"(c[3])
        : "r"(a[0]), "r"(a[1]), "r"(a[2]), "r"(a[3]), "r"(b[0]), "r"(b[1]));
}

__global__ __launch_bounds__(NT, 2)
void mm_kernel(const float* __restrict__ bias, float* __restrict__ out) {
    int b = blockIdx.x;
    if (b >= g_ntiles) return;
    int e = g_tile_e[b];
    int m0 = g_tile_m0[b];
    int mcnt = g_tile_mc[b];

    extern __shared__ char smem[];
    uint32_t sb = smem_u32(smem);
    int t = threadIdx.x;
    int wid = t >> 5;
    int lane = t & 31;

    // ---- Stage B immediately ----
    #pragma unroll
    for (int i = t; i < DIN * 16; i += NT) {
        int k = i >> 4;
        int c = i & 15;
        uint32_t doff = (uint32_t)(k * LDA + c * 8) * 2;
        size_t soff = (size_t)e * DIN * DOUT + (size_t)k * DOUT + c * 8;
        cp16(sb + SB_HI + doff, g_whi + soff);
        cp16(sb + SB_LO + doff, g_wlo + soff);
    }
    // ---- Stage A (row ids read directly from gmem; broadcast within 16-thread groups) ----
    #pragma unroll
    for (int i = t; i < TILE_M * 16; i += NT) {
        int m = i >> 4;
        int c = i & 15;
        int gr = g_rowids[m0 + min(m, mcnt - 1)];
        uint32_t doff = (uint32_t)(m * LDA + c * 8) * 2;
        cp16(sb + SA_HI + doff, g_xhi + (size_t)gr * DIN + c * 8);
        cp16(sb + SA_LO + doff, g_xlo + (size_t)gr * DIN + c * 8);
    }
    asm volatile("cp.async.commit_group;" ::: "memory");

    int* srow = (int*)(smem + SROW);
    float* sbias = (float*)(smem + SBIAS);
    if (t < TILE_M) srow[t] = g_rowids[m0 + min(t, mcnt - 1)];
    if (t >= 64 && t < 64 + DOUT) sbias[t - 64] = bias[(size_t)e * DOUT + t - 64];

    asm volatile("cp.async.wait_group 0;" ::: "memory");
    __syncthreads();

    // ---- MMA mainloop (unchanged) ----
    int warp_m = wid & 1;
    int warp_n = wid >> 1;

    float acc[2][4][4];
    #pragma unroll
    for (int mt = 0; mt < 2; mt++)
        #pragma unroll
        for (int nt = 0; nt < 4; nt++)
            #pragma unroll
            for (int j = 0; j < 4; j++) acc[mt][nt][j] = 0.0f;

    int a_r = warp_m * 32 + (lane & 15);
    int a_c8 = (lane >> 4) << 3;
    int b_rk = (lane & 7) + (((lane >> 3) & 1) << 3);
    int b_c8 = (lane >> 4) << 3;

    #pragma unroll
    for (int ks = 0; ks < 8; ks++) {
        int k0 = ks * 16;
        uint32_t Ah[2][4], Al[2][4];
        #pragma unroll
        for (int mt = 0; mt < 2; mt++) {
            uint32_t aoff = (uint32_t)((a_r + mt * 16) * LDA + k0 + a_c8) * 2;
            ldsm_x4(Ah[mt], sb + SA_HI + aoff);
            ldsm_x4(Al[mt], sb + SA_LO + aoff);
        }
        #pragma unroll
        for (int np = 0; np < 2; np++) {
            int n0 = warp_n * 32 + np * 16;
            uint32_t boff = (uint32_t)((k0 + b_rk) * LDA + n0 + b_c8) * 2;
            uint32_t Bh[4], Bl[4];
            ldsm_x4t(Bh, sb + SB_HI + boff);
            ldsm_x4t(Bl, sb + SB_LO + boff);
            #pragma unroll
            for (int mt = 0; mt < 2; mt++) {
                mma_bf16(acc[mt][2 * np + 0], Ah[mt], Bh + 0);
                mma_bf16(acc[mt][2 * np + 1], Ah[mt], Bh + 2);
                mma_bf16(acc[mt][2 * np + 0], Ah[mt], Bl + 0);
                mma_bf16(acc[mt][2 * np + 1], Ah[mt], Bl + 2);
                mma_bf16(acc[mt][2 * np + 0], Al[mt], Bh + 0);
                mma_bf16(acc[mt][2 * np + 1], Al[mt], Bh + 2);
            }
        }
    }

    // ---- Epilogue: bias + scatter to out rows ----
    int g4 = lane >> 2;
    int t4 = lane & 3;
    #pragma unroll
    for (int mt = 0; mt < 2; mt++) {
        #pragma unroll
        for (int half = 0; half < 2; half++) {
            int m = warp_m * 32 + mt * 16 + half * 8 + g4;
            if (m < mcnt) {
                int gr = srow[m];
                float* orow = out + (size_t)gr * DOUT;
                #pragma unroll
                for (int nt = 0; nt < 4; nt++) {
                    int c = warp_n * 32 + nt * 8 + t4 * 2;
                    float2 v;
                    v.x = acc[mt][nt][half * 2 + 0] + sbias[c];
                    v.y = acc[mt][nt][half * 2 + 1] + sbias[c + 1];
                    *(float2*)(orow + c) = v;
                }
            }
        }
    }
}

extern "C" void kernel_launch(void* const* d_in, const int* in_sizes, int n_in,
                              void* d_out, int out_size) {
    const float* x = (const float*)d_in[0];
    const float* w = (const float*)d_in[1];
    const float* b = (const float*)d_in[2];
    const int* idx = (const int*)d_in[3];   // JAX x64-disabled: indices arrive int32
    float* out = (float*)d_out;
    int B = in_sizes[3];
    if (B > MAX_B) B = MAX_B;

    cudaFuncSetAttribute(mm_kernel, cudaFuncAttributeMaxDynamicSharedMemorySize,
                         SMEM_BYTES);

    prep_kernel<<<K1_BLOCKS, 256>>>(idx, x, w, B);
    mm_kernel<<<MAX_TILES, NT, SMEM_BYTES>>>(b, out);
}

// round 15
// speedup vs baseline: 1.5342x; 1.5342x over previous
#include <cuda_runtime.h>
#include <cuda_bf16.h>
#include <cstdint>

#define OPT 64
#define DIN 128
#define DOUT 128
#define TILE_M 64
#define MAX_B 16384
#define HBLK 16
#define MAX_TILES (MAX_B / TILE_M + OPT)      // 320

// ---- scratch (device allocation banned) ----
__device__ int g_blockhist[HBLK][OPT];
__device__ int g_rowids[MAX_B];
__device__ int g_scatter_done;
// pre-split bf16 operands
__device__ __align__(16) __nv_bfloat16 g_xhi[MAX_B * DIN];
__device__ __align__(16) __nv_bfloat16 g_xlo[MAX_B * DIN];
__device__ __align__(16) __nv_bfloat16 g_whi[OPT * DIN * DOUT];
__device__ __align__(16) __nv_bfloat16 g_wlo[OPT * DIN * DOUT];

__device__ __forceinline__ uint32_t pack_bf2(__nv_bfloat16 lo, __nv_bfloat16 hi) {
    return ((uint32_t)__bfloat16_as_ushort(hi) << 16) | __bfloat16_as_ushort(lo);
}

__device__ __forceinline__ void split8(const float* vv, uint4& ph4, uint4& pl4) {
    uint32_t ph[4], pl[4];
    #pragma unroll
    for (int j = 0; j < 4; j++) {
        __nv_bfloat16 h0 = __float2bfloat16_rn(vv[2 * j]);
        __nv_bfloat16 h1 = __float2bfloat16_rn(vv[2 * j + 1]);
        __nv_bfloat16 l0 = __float2bfloat16_rn(vv[2 * j] - __bfloat162float(h0));
        __nv_bfloat16 l1 = __float2bfloat16_rn(vv[2 * j + 1] - __bfloat162float(h1));
        ph[j] = pack_bf2(h0, h1);
        pl[j] = pack_bf2(l0, l1);
    }
    ph4 = make_uint4(ph[0], ph[1], ph[2], ph[3]);
    pl4 = make_uint4(pl[0], pl[1], pl[2], pl[3]);
}

// ---------------- K1: hist (blocks 0..15) + convert x,w (blocks 16..255) ------------

#define K1_BLOCKS 256

__global__ void hist_conv_kernel(const int* __restrict__ idx,
                                 const float* __restrict__ x,
                                 const float* __restrict__ w, int B) {
    int t = threadIdx.x;
    int b = blockIdx.x;
    if (b == 0 && t == 0) g_scatter_done = 0;   // reset for this replay
    if (b < HBLK) {
        __shared__ int h[OPT];
        if (t < OPT) h[t] = 0;
        __syncthreads();
        int i4 = b * 256 + t;
        if (i4 * 4 + 3 < B) {
            int4 v = ((const int4*)idx)[i4];
            if (v.x >= 0 && v.x < OPT) atomicAdd(&h[v.x], 1);
            if (v.y >= 0 && v.y < OPT) atomicAdd(&h[v.y], 1);
            if (v.z >= 0 && v.z < OPT) atomicAdd(&h[v.z], 1);
            if (v.w >= 0 && v.w < OPT) atomicAdd(&h[v.w], 1);
        } else {
            for (int i = i4 * 4; i < min(i4 * 4 + 4, B); i++) {
                int e = idx[i];
                if (e >= 0 && e < OPT) atomicAdd(&h[e], 1);
            }
        }
        __syncthreads();
        if (t < OPT) g_blockhist[b][t] = h[t];
    } else {
        int nxc = B * DIN / 8;
        int nwc = OPT * DIN * DOUT / 8;
        int start = (b - HBLK) * 256 + t;
        int stride = (K1_BLOCKS - HBLK) * 256;
        for (int i = start; i < nxc + nwc; i += stride) {
            if (i < nxc) {
                const float* s = x + (size_t)i * 8;
                float4 v0 = *(const float4*)(s);
                float4 v1 = *(const float4*)(s + 4);
                float vv[8] = {v0.x, v0.y, v0.z, v0.w, v1.x, v1.y, v1.z, v1.w};
                uint4 ph4, pl4;
                split8(vv, ph4, pl4);
                *(uint4*)(g_xhi + (size_t)i * 8) = ph4;
                *(uint4*)(g_xlo + (size_t)i * 8) = pl4;
            } else {
                size_t j = (size_t)(i - nxc) * 8;
                const float* s = w + j;
                float4 v0 = *(const float4*)(s);
                float4 v1 = *(const float4*)(s + 4);
                float vv[8] = {v0.x, v0.y, v0.z, v0.w, v1.x, v1.y, v1.z, v1.w};
                uint4 ph4, pl4;
                split8(vv, ph4, pl4);
                *(uint4*)(g_whi + j) = ph4;
                *(uint4*)(g_wlo + j) = pl4;
            }
        }
    }
}

// ---------------- K2: fused scan + scatter + mm ----------------
// Tile 64(M) x 128(N) x 128(K). 8 warps 2x4. 2 blocks/SM.

#define LDA 136
#define SA_HI 0
#define SA_LO (TILE_M * LDA * 2)                      // 17408
#define SB_HI (2 * TILE_M * LDA * 2)                  // 34816
#define SB_LO (2 * TILE_M * LDA * 2 + DIN * LDA * 2)  // 69632
#define SROW  (2 * TILE_M * LDA * 2 + 2 * DIN * LDA * 2)  // 104448
#define SBIAS (SROW + 256)
#define SSCAN (SBIAS + 512)   // tot[64] off[64] toff[64] cur[64] meta[8]
#define SMEM_BYTES (SSCAN + 1536)
#define NT 256

__device__ __forceinline__ uint32_t smem_u32(const void* p) {
    uint32_t a;
    asm("{ .reg .u64 tmp; cvta.to.shared.u64 tmp, %1; cvt.u32.u64 %0, tmp; }"
        : "=r"(a) : "l"(p));
    return a;
}

__device__ __forceinline__ void cp16(uint32_t dst, const void* src) {
    asm volatile("cp.async.cg.shared.global [%0], [%1], 16;"
                 :: "r"(dst), "l"(src) : "memory");
}

__device__ __forceinline__ void ldsm_x4(uint32_t* r, uint32_t addr) {
    asm volatile("ldmatrix.sync.aligned.m8n8.x4.shared.b16 {%0,%1,%2,%3}, [%4];"
        : "=r"(r[0]), "=r"(r[1]), "=r"(r[2]), "=r"(r[3]) : "r"(addr));
}

__device__ __forceinline__ void ldsm_x4t(uint32_t* r, uint32_t addr) {
    asm volatile("ldmatrix.sync.aligned.m8n8.x4.trans.shared.b16 {%0,%1,%2,%3}, [%4];"
        : "=r"(r[0]), "=r"(r[1]), "=r"(r[2]), "=r"(r[3]) : "r"(addr));
}

__device__ __forceinline__ void mma_bf16(float* c, const uint32_t* a, const uint32_t* b) {
    asm volatile(
        "mma.sync.aligned.m16n8k16.row.col.f32.bf16.bf16.f32 "
        "{%0,%1,%2,%3}, {%4,%5,%6,%7}, {%8,%9}, {%0,%1,%2,%3};"
        : "+f"(c[0]), "+f"(c[1]), "+f"(c[2]), "+f"(c[3])
        : "r"(a[0]), "r"(a[1]), "r"(a[2]), "r"(a[3]), "r"(b[0]), "r"(b[1]));
}

__global__ __launch_bounds__(NT, 2)
void mm_fused_kernel(const int* __restrict__ idx, const float* __restrict__ bias,
                     float* __restrict__ out, int B) {
    extern __shared__ char smem[];
    uint32_t sb = smem_u32(smem);
    int t = threadIdx.x;
    int b = blockIdx.x;
    int wid = t >> 5;
    int lane = t & 31;

    int* tot  = (int*)(smem + SSCAN);
    int* off  = tot + 64;
    int* toff = off + 64;
    int* cur  = toff + 64;
    int* meta = cur + 64;

    // ---- parallel scan: row offsets + tile offsets (2 warps, dual shfl scan) ----
    if (t == 64) meta[0] = -1;
    if (t < OPT) {
        int s = 0;
        #pragma unroll
        for (int bb = 0; bb < HBLK; bb++) s += g_blockhist[bb][t];
        int nte = (s + TILE_M - 1) >> 6;
        int v1 = s, v2 = nte;
        #pragma unroll
        for (int d = 1; d < 32; d <<= 1) {
            int n1 = __shfl_up_sync(0xffffffffu, v1, d);
            int n2 = __shfl_up_sync(0xffffffffu, v2, d);
            if (lane >= d) { v1 += n1; v2 += n2; }
        }
        tot[t] = s;
        off[t] = v1 - s;
        toff[t] = v2 - nte;
        if (t == 31) { meta[4] = v1; meta[5] = v2; }   // warp-0 totals
    }
    __syncthreads();
    if (t >= 32 && t < 64) { off[t] += meta[4]; toff[t] += meta[5]; }
    __syncthreads();

    // ---- tile lookup (O(1) per expert-thread) ----
    if (t < OPT) {
        int ts = toff[t];
        int nte = (tot[t] + TILE_M - 1) >> 6;
        if (b >= ts && b < ts + nte) { meta[0] = t; meta[1] = off[t] + (b - ts) * TILE_M; }
    }
    __syncthreads();
    int e = meta[0];
    if (e < 0) return;
    int m0 = meta[1];
    int mcnt = min(TILE_M, off[e] + tot[e] - m0);

    // ---- scatter duty (blocks 0..15) ----
    if (b < HBLK) {
        if (t < OPT) {
            int pre = off[t];
            for (int bb = 0; bb < b; bb++) pre += g_blockhist[bb][t];
            cur[t] = pre;
        }
        __syncthreads();
        int i4 = b * 256 + t;
        if (i4 * 4 + 3 < B) {
            int4 v = ((const int4*)idx)[i4];
            int es[4] = {v.x, v.y, v.z, v.w};
            #pragma unroll
            for (int j = 0; j < 4; j++) {
                int e2 = es[j];
                if (e2 >= 0 && e2 < OPT) {
                    int r = atomicAdd(&cur[e2], 1);
                    g_rowids[r] = i4 * 4 + j;
                }
            }
        } else {
            for (int i = i4 * 4; i < min(i4 * 4 + 4, B); i++) {
                int e2 = idx[i];
                if (e2 >= 0 && e2 < OPT) {
                    int r = atomicAdd(&cur[e2], 1);
                    g_rowids[r] = i;
                }
            }
        }
        __threadfence();
        __syncthreads();
        if (t == 0) atomicAdd(&g_scatter_done, 1);
    }

    // ---- Stage B immediately via cp.async (independent of scatter) ----
    #pragma unroll
    for (int i = t; i < DIN * 16; i += NT) {
        int k = i >> 4;
        int c = i & 15;
        uint32_t doff = (uint32_t)(k * LDA + c * 8) * 2;
        size_t soff = (size_t)e * DIN * DOUT + (size_t)k * DOUT + c * 8;
        cp16(sb + SB_HI + doff, g_whi + soff);
        cp16(sb + SB_LO + doff, g_wlo + soff);
    }
    asm volatile("cp.async.commit_group;" ::: "memory");

    float* sbias = (float*)(smem + SBIAS);
    if (t >= 64 && t < 64 + DOUT) sbias[t - 64] = bias[(size_t)e * DOUT + t - 64];

    // ---- wait for scatter completion (B copy in flight meanwhile) ----
    if (t == 0) {
        int v;
        do {
            asm volatile("ld.global.acquire.gpu.b32 %0, [%1];"
                         : "=r"(v) : "l"(&g_scatter_done) : "memory");
        } while (v < HBLK);
    }
    __syncthreads();

    int* srow = (int*)(smem + SROW);
    if (t < TILE_M) srow[t] = g_rowids[m0 + min(t, mcnt - 1)];
    __syncthreads();

    // ---- Stage A via cp.async ----
    #pragma unroll
    for (int i = t; i < TILE_M * 16; i += NT) {
        int m = i >> 4;
        int c = i & 15;
        int gr = srow[m];
        uint32_t doff = (uint32_t)(m * LDA + c * 8) * 2;
        cp16(sb + SA_HI + doff, g_xhi + (size_t)gr * DIN + c * 8);
        cp16(sb + SA_LO + doff, g_xlo + (size_t)gr * DIN + c * 8);
    }
    asm volatile("cp.async.commit_group;" ::: "memory");
    asm volatile("cp.async.wait_group 0;" ::: "memory");
    __syncthreads();

    // ---- MMA mainloop: term-grouped issue to break acc chains ----
    int warp_m = wid & 1;
    int warp_n = wid >> 1;

    float acc[2][4][4];
    #pragma unroll
    for (int mt = 0; mt < 2; mt++)
        #pragma unroll
        for (int nt = 0; nt < 4; nt++)
            #pragma unroll
            for (int j = 0; j < 4; j++) acc[mt][nt][j] = 0.0f;

    int a_r = warp_m * 32 + (lane & 15);
    int a_c8 = (lane >> 4) << 3;
    int b_rk = (lane & 7) + (((lane >> 3) & 1) << 3);
    int b_c8 = (lane >> 4) << 3;

    #pragma unroll
    for (int ks = 0; ks < 8; ks++) {
        int k0 = ks * 16;
        uint32_t Ah[2][4], Al[2][4], Bh[2][4], Bl[2][4];
        #pragma unroll
        for (int mt = 0; mt < 2; mt++) {
            uint32_t aoff = (uint32_t)((a_r + mt * 16) * LDA + k0 + a_c8) * 2;
            ldsm_x4(Ah[mt], sb + SA_HI + aoff);
            ldsm_x4(Al[mt], sb + SA_LO + aoff);
        }
        #pragma unroll
        for (int np = 0; np < 2; np++) {
            int n0 = warp_n * 32 + np * 16;
            uint32_t boff = (uint32_t)((k0 + b_rk) * LDA + n0 + b_c8) * 2;
            ldsm_x4t(Bh[np], sb + SB_HI + boff);
            ldsm_x4t(Bl[np], sb + SB_LO + boff);
        }
        // group 1: hiA * hiB  (8 independent acc frags)
        #pragma unroll
        for (int np = 0; np < 2; np++)
            #pragma unroll
            for (int mt = 0; mt < 2; mt++) {
                mma_bf16(acc[mt][2 * np + 0], Ah[mt], Bh[np] + 0);
                mma_bf16(acc[mt][2 * np + 1], Ah[mt], Bh[np] + 2);
            }
        // group 2: hiA * loB
        #pragma unroll
        for (int np = 0; np < 2; np++)
            #pragma unroll
            for (int mt = 0; mt < 2; mt++) {
                mma_bf16(acc[mt][2 * np + 0], Ah[mt], Bl[np] + 0);
                mma_bf16(acc[mt][2 * np + 1], Ah[mt], Bl[np] + 2);
            }
        // group 3: loA * hiB
        #pragma unroll
        for (int np = 0; np < 2; np++)
            #pragma unroll
            for (int mt = 0; mt < 2; mt++) {
                mma_bf16(acc[mt][2 * np + 0], Al[mt], Bh[np] + 0);
                mma_bf16(acc[mt][2 * np + 1], Al[mt], Bh[np] + 2);
            }
    }

    // ---- Epilogue: bias + scatter to out rows ----
    int g4 = lane >> 2;
    int t4 = lane & 3;
    #pragma unroll
    for (int mt = 0; mt < 2; mt++) {
        #pragma unroll
        for (int half = 0; half < 2; half++) {
            int m = warp_m * 32 + mt * 16 + half * 8 + g4;
            if (m < mcnt) {
                int gr = srow[m];
                float* orow = out + (size_t)gr * DOUT;
                #pragma unroll
                for (int nt = 0; nt < 4; nt++) {
                    int c = warp_n * 32 + nt * 8 + t4 * 2;
                    float2 v;
                    v.x = acc[mt][nt][half * 2 + 0] + sbias[c];
                    v.y = acc[mt][nt][half * 2 + 1] + sbias[c + 1];
                    *(float2*)(orow + c) = v;
                }
            }
        }
    }
}

extern "C" void kernel_launch(void* const* d_in, const int* in_sizes, int n_in,
                              void* d_out, int out_size) {
    const float* x = (const float*)d_in[0];
    const float* w = (const float*)d_in[1];
    const float* b = (const float*)d_in[2];
    const int* idx = (const int*)d_in[3];   // JAX x64-disabled: indices arrive int32
    float* out = (float*)d_out;
    int B = in_sizes[3];
    if (B > MAX_B) B = MAX_B;

    cudaFuncSetAttribute(mm_fused_kernel, cudaFuncAttributeMaxDynamicSharedMemorySize,
                         SMEM_BYTES);

    hist_conv_kernel<<<K1_BLOCKS, 256>>>(idx, x, w, B);
    mm_fused_kernel<<<MAX_TILES, NT, SMEM_BYTES>>>(idx, b, out, B);
}